// round 7
// baseline (speedup 1.0000x reference)
#include <cuda_runtime.h>
#include <cuda_fp16.h>
#include <cstdint>
#include <math.h>

// ---------------- problem dims ----------------
#define BB 8
#define SLQ 2048
#define SLK 2048
#define DQ 1024
#define DK 512
#define DV 512
#define MFLAT (BB * SLQ)          // 16384

typedef __half f16;

// ---------------- scratch (device globals; allocation-free rule) ------------
__device__ __align__(256) f16 g_wq_hi[(size_t)DQ * DQ];
__device__ __align__(256) f16 g_wq_lo[(size_t)DQ * DQ];
__device__ __align__(256) f16 g_wk_hi[(size_t)DK * DQ];
__device__ __align__(256) f16 g_wk_lo[(size_t)DK * DQ];
__device__ __align__(256) f16 g_wvt_hi[(size_t)DQ * DV];      // Wv^T [1024,512]
__device__ __align__(256) f16 g_wvt_lo[(size_t)DQ * DV];
__device__ __align__(256) f16 g_vt_hi[(size_t)BB * DV * SLK]; // value^T [B,512,2048]
__device__ __align__(256) f16 g_vt_lo[(size_t)BB * DV * SLK];
__device__ __align__(256) f16 g_mt_hi[(size_t)DK * DQ];       // Mt = Wk Wq^T
__device__ __align__(256) f16 g_mt_lo[(size_t)DK * DQ];
__device__ __align__(256) f16 g_t_hi[(size_t)MFLAT * DK];     // T = q Mt^T (hi only)
__device__ __align__(256) f16 g_u_hi[(size_t)MFLAT * DV];     // U = P v
__device__ __align__(256) f16 g_u_lo[(size_t)MFLAT * DV];
__device__ __align__(256) float g_s[(size_t)BB * SLQ * SLK];  // scores fp32
__device__ __align__(256) f16 g_p_hi[(size_t)BB * SLQ * SLK]; // probs (hi only)
__device__ __align__(256) float g_wbq[DK];
__device__ __align__(256) float g_vvec[MFLAT];

// ---------------- small helpers ----------------
__device__ __forceinline__ uint32_t smem_u32(const void* p) {
    uint32_t a;
    asm("{ .reg .u64 t; cvta.to.shared.u64 t, %1; cvt.u32.u64 %0, t; }" : "=r"(a) : "l"(p));
    return a;
}
// pack: low half <- lo_f, high half <- hi_f
__device__ __forceinline__ uint32_t packh(float hi_f, float lo_f) {
    uint32_t r;
    asm("cvt.rn.f16x2.f32 %0, %1, %2;" : "=r"(r) : "f"(hi_f), "f"(lo_f));
    return r;
}
__device__ __forceinline__ float2 h2f(uint32_t p) {
    __half2 h = *reinterpret_cast<__half2*>(&p);
    return __half22float2(h);
}
__device__ __forceinline__ void cp16(uint32_t dst, const void* src) {
    asm volatile("cp.async.cg.shared.global [%0], [%1], 16;" :: "r"(dst), "l"(src));
}
__device__ __forceinline__ void ldm4(uint32_t (&r)[4], uint32_t a) {
    asm volatile("ldmatrix.sync.aligned.m8n8.x4.shared.b16 {%0,%1,%2,%3}, [%4];"
                 : "=r"(r[0]), "=r"(r[1]), "=r"(r[2]), "=r"(r[3]) : "r"(a));
}
__device__ __forceinline__ void mma16816(float* d, const uint32_t* a, uint32_t b0, uint32_t b1) {
    asm volatile("mma.sync.aligned.m16n8k16.row.col.f32.f16.f16.f32 "
                 "{%0,%1,%2,%3}, {%4,%5,%6,%7}, {%8,%9}, {%0,%1,%2,%3};"
                 : "+f"(d[0]), "+f"(d[1]), "+f"(d[2]), "+f"(d[3])
                 : "r"(a[0]), "r"(a[1]), "r"(a[2]), "r"(a[3]), "r"(b0), "r"(b1));
}

#define ROWB   80
#define TILEB  (128 * ROWB)

// ============================================================================
// P3 GEMM (warp tile 32x64): C = A B^T, products AhBh + AhBl + AlBh.
// AF32: A side from fp32, split in-kernel.
// MODE 0: fp32 out (+bias). MODE 1: split f16 hi/lo out. MODE 2: f16 hi out.
// ============================================================================
template <int MODE, int AF32>
__global__ __launch_bounds__(256, 2) void gemm_mma(
    const f16* __restrict__ Ahi, const f16* __restrict__ Alo,
    const float* __restrict__ A32,
    const f16* __restrict__ Bhi, const f16* __restrict__ Blo,
    const float* __restrict__ bias,
    float* __restrict__ Cf, f16* __restrict__ Chi, f16* __restrict__ Clo,
    int M, int N, int K, size_t sA, size_t sB, size_t sC)
{
    constexpr int STAGE = 4 * TILEB;
    constexpr int SCRO = 2 * STAGE;
    constexpr int NF16 = AF32 ? 2 : 4;

    extern __shared__ char smem[];
    const uint32_t sb = smem_u32(smem);
    const int tid = threadIdx.x, wid = tid >> 5, lane = tid & 31;
    const int bz = blockIdx.z;
    const int bm = blockIdx.y * 128, bn = blockIdx.x * 128;

    const f16* s16[NF16];
    int d16[NF16];
    if (AF32) {
        s16[0] = Bhi + (size_t)bz * sB + (size_t)bn * K; d16[0] = 2;
        s16[1] = Blo + (size_t)bz * sB + (size_t)bn * K; d16[1] = 3;
    } else {
        s16[0] = Ahi + (size_t)bz * sA + (size_t)bm * K; d16[0] = 0;
        s16[1] = Alo + (size_t)bz * sA + (size_t)bm * K; d16[1] = 1;
        s16[2] = Bhi + (size_t)bz * sB + (size_t)bn * K; d16[2] = 2;
        s16[3] = Blo + (size_t)bz * sB + (size_t)bn * K; d16[3] = 3;
    }
    const float* s32 = AF32 ? (A32 + (size_t)bz * sA + (size_t)bm * K) : nullptr;

    const int wm = wid & 3, wn = wid >> 2;    // warp tile 32(M) x 64(N)
    const uint32_t a_l = (uint32_t)((wm * 32 + (lane & 7) + ((lane >> 3) & 1) * 8) * ROWB
                                    + ((lane >> 4) & 1) * 16);
    const uint32_t b_l = (uint32_t)((wn * 64 + (lane & 7) + ((lane >> 4) & 1) * 8) * ROWB
                                    + ((lane >> 3) & 1) * 16);

    float acc[2][8][4];
#pragma unroll
    for (int m = 0; m < 2; m++)
#pragma unroll
        for (int n = 0; n < 8; n++)
#pragma unroll
            for (int j = 0; j < 4; j++) acc[m][n][j] = 0.0f;

    const int nc = K >> 5;

    auto load_stage = [&](int c, int stage) {
        const int k0 = c << 5;
#pragma unroll
        for (int t = 0; t < 2 * NF16; t++) {
            const int idx = tid + t * 256;
            const int tile = idx >> 9;
            const int r = (idx >> 2) & 127;
            const int ch = idx & 3;
            cp16(sb + stage * STAGE + d16[tile] * TILEB + r * ROWB + ch * 16,
                 s16[tile] + (size_t)r * K + k0 + ch * 8);
        }
        if (AF32) {
#pragma unroll
            for (int t = 0; t < 4; t++) {
                const int idx = tid + t * 256;
                const int r = idx >> 3;
                const int c4 = idx & 7;
                cp16(sb + SCRO + r * 128 + c4 * 16,
                     s32 + (size_t)r * K + k0 + c4 * 4);
            }
        }
        asm volatile("cp.async.commit_group;" ::: "memory");
    };

    auto convert_stage = [&](int stage) {
#pragma unroll
        for (int t = 0; t < 4; t++) {
            const int idx = tid + t * 256;
            const int r = idx >> 3;
            const int c4 = idx & 7;
            const float4 v = *(const float4*)(smem + SCRO + r * 128 + c4 * 16);
            const uint32_t h01 = packh(v.y, v.x);
            const uint32_t h23 = packh(v.w, v.z);
            const float2 f01 = h2f(h01), f23 = h2f(h23);
            const uint32_t l01 = packh(v.y - f01.y, v.x - f01.x);
            const uint32_t l23 = packh(v.w - f23.y, v.z - f23.x);
            const int off = stage * STAGE + r * ROWB + c4 * 8;
            *(uint2*)(smem + off + 0 * TILEB) = make_uint2(h01, h23);
            *(uint2*)(smem + off + 1 * TILEB) = make_uint2(l01, l23);
        }
    };

    auto compute_stage = [&](int stage) {
        const uint32_t base = sb + stage * STAGE;
#pragma unroll
        for (int ks = 0; ks < 2; ks++) {
            const uint32_t koff = ks * 32;
            uint32_t ah[2][4], al[2][4];
            ldm4(ah[0], base + a_l + koff);
            ldm4(ah[1], base + a_l + koff + 16 * ROWB);
            ldm4(al[0], base + 1 * TILEB + a_l + koff);
            ldm4(al[1], base + 1 * TILEB + a_l + koff + 16 * ROWB);
#pragma unroll
            for (int g = 0; g < 4; g++) {
                uint32_t bh[4], bl[4];
                ldm4(bh, base + 2 * TILEB + b_l + koff + g * 16 * ROWB);
                ldm4(bl, base + 3 * TILEB + b_l + koff + g * 16 * ROWB);
                // product-class sweeps: per-acc order hh -> hl -> lh preserved,
                // dependent writes >= 4 MMAs apart.
#pragma unroll
                for (int m = 0; m < 2; m++) {
                    mma16816(acc[m][2 * g],     ah[m], bh[0], bh[1]);
                    mma16816(acc[m][2 * g + 1], ah[m], bh[2], bh[3]);
                }
#pragma unroll
                for (int m = 0; m < 2; m++) {
                    mma16816(acc[m][2 * g],     ah[m], bl[0], bl[1]);
                    mma16816(acc[m][2 * g + 1], ah[m], bl[2], bl[3]);
                }
#pragma unroll
                for (int m = 0; m < 2; m++) {
                    mma16816(acc[m][2 * g],     al[m], bh[0], bh[1]);
                    mma16816(acc[m][2 * g + 1], al[m], bh[2], bh[3]);
                }
            }
        }
    };

    load_stage(0, 0);

    for (int c = 0; c < nc; c++) {
        const int stage = c & 1;
        if (AF32) {
            asm volatile("cp.async.wait_group 0;" ::: "memory");
            __syncthreads();
            convert_stage(stage);
            __syncthreads();
            if (c + 1 < nc) load_stage(c + 1, stage ^ 1);
            compute_stage(stage);
        } else {
            if (c + 1 < nc) {
                load_stage(c + 1, stage ^ 1);
                asm volatile("cp.async.wait_group 1;" ::: "memory");
            } else {
                asm volatile("cp.async.wait_group 0;" ::: "memory");
            }
            __syncthreads();
            compute_stage(stage);
            __syncthreads();
        }
    }

    // ---- epilogue ----
    const int row0 = bm + wm * 32 + (lane >> 2);
    const int col0 = bn + wn * 64 + (lane & 3) * 2;
#pragma unroll
    for (int m = 0; m < 2; m++) {
#pragma unroll
        for (int nt = 0; nt < 8; nt++) {
            const int r = row0 + m * 16;
            const int cc = col0 + nt * 8;
            float b0 = 0.f, b1 = 0.f;
            if (bias) { b0 = bias[cc]; b1 = bias[cc + 1]; }
            const float x0 = acc[m][nt][0] + b0, x1 = acc[m][nt][1] + b1;
            const float y0 = acc[m][nt][2] + b0, y1 = acc[m][nt][3] + b1;
            if (MODE == 0) {
                *(float2*)(Cf + (size_t)bz * sC + (size_t)r * N + cc) = make_float2(x0, x1);
                *(float2*)(Cf + (size_t)bz * sC + (size_t)(r + 8) * N + cc) = make_float2(y0, y1);
            } else if (MODE == 2) {
                *(uint32_t*)(Chi + (size_t)bz * sC + (size_t)r * N + cc) = packh(x1, x0);
                *(uint32_t*)(Chi + (size_t)bz * sC + (size_t)(r + 8) * N + cc) = packh(y1, y0);
            } else {
                const uint32_t hx = packh(x1, x0);
                const float2 fx = h2f(hx);
                const uint32_t lx = packh(x1 - fx.y, x0 - fx.x);
                const uint32_t hy = packh(y1, y0);
                const float2 fy = h2f(hy);
                const uint32_t ly = packh(y1 - fy.y, y0 - fy.x);
                *(uint32_t*)(Chi + (size_t)bz * sC + (size_t)r * N + cc) = hx;
                *(uint32_t*)(Clo + (size_t)bz * sC + (size_t)r * N + cc) = lx;
                *(uint32_t*)(Chi + (size_t)bz * sC + (size_t)(r + 8) * N + cc) = hy;
                *(uint32_t*)(Clo + (size_t)bz * sC + (size_t)(r + 8) * N + cc) = ly;
            }
        }
    }
}

// ============================================================================
// P2 GEMM (warp tile 64x32, 2x4 warp grid): products AhBh + AhBl (A single f16).
// BF32: B side from fp32, split in-kernel.
// MODE 0: fp32 out. MODE 1: split f16 hi/lo out.
// ============================================================================
template <int MODE, int BF32>
__global__ __launch_bounds__(256, 2) void gemm_mma2(
    const f16* __restrict__ Ahi,
    const f16* __restrict__ Bhi, const f16* __restrict__ Blo,
    const float* __restrict__ B32,
    float* __restrict__ Cf, f16* __restrict__ Chi, f16* __restrict__ Clo,
    int M, int N, int K, size_t sA, size_t sB, size_t sC)
{
    constexpr int STAGE = 3 * TILEB;
    constexpr int SCRO = 2 * STAGE;
    constexpr int NF16 = BF32 ? 1 : 3;

    extern __shared__ char smem[];
    const uint32_t sb = smem_u32(smem);
    const int tid = threadIdx.x, wid = tid >> 5, lane = tid & 31;
    const int bz = blockIdx.z;
    const int bm = blockIdx.y * 128, bn = blockIdx.x * 128;

    const f16* s16[NF16];
    int d16[NF16];
    s16[0] = Ahi + (size_t)bz * sA + (size_t)bm * K; d16[0] = 0;
    if (!BF32) {
        s16[1] = Bhi + (size_t)bz * sB + (size_t)bn * K; d16[1] = 1;
        s16[2] = Blo + (size_t)bz * sB + (size_t)bn * K; d16[2] = 2;
    }
    const float* s32 = BF32 ? (B32 + (size_t)bz * sB + (size_t)bn * K) : nullptr;

    const int wm = wid & 1, wn = wid >> 1;    // warp tile 64(M) x 32(N)
    const uint32_t a_l = (uint32_t)((wm * 64 + (lane & 7) + ((lane >> 3) & 1) * 8) * ROWB
                                    + ((lane >> 4) & 1) * 16);
    const uint32_t b_l = (uint32_t)((wn * 32 + (lane & 7) + ((lane >> 4) & 1) * 8) * ROWB
                                    + ((lane >> 3) & 1) * 16);

    float acc[4][4][4];
#pragma unroll
    for (int m = 0; m < 4; m++)
#pragma unroll
        for (int n = 0; n < 4; n++)
#pragma unroll
            for (int j = 0; j < 4; j++) acc[m][n][j] = 0.0f;

    const int nc = K >> 5;

    auto load_stage = [&](int c, int stage) {
        const int k0 = c << 5;
#pragma unroll
        for (int t = 0; t < 2 * NF16; t++) {
            const int idx = tid + t * 256;
            const int tile = idx >> 9;
            const int r = (idx >> 2) & 127;
            const int ch = idx & 3;
            cp16(sb + stage * STAGE + d16[tile] * TILEB + r * ROWB + ch * 16,
                 s16[tile] + (size_t)r * K + k0 + ch * 8);
        }
        if (BF32) {
#pragma unroll
            for (int t = 0; t < 4; t++) {
                const int idx = tid + t * 256;
                const int r = idx >> 3;
                const int c4 = idx & 7;
                cp16(sb + SCRO + r * 128 + c4 * 16,
                     s32 + (size_t)r * K + k0 + c4 * 4);
            }
        }
        asm volatile("cp.async.commit_group;" ::: "memory");
    };

    auto convert_stage = [&](int stage) {
#pragma unroll
        for (int t = 0; t < 4; t++) {
            const int idx = tid + t * 256;
            const int r = idx >> 3;
            const int c4 = idx & 7;
            const float4 v = *(const float4*)(smem + SCRO + r * 128 + c4 * 16);
            const uint32_t h01 = packh(v.y, v.x);
            const uint32_t h23 = packh(v.w, v.z);
            const float2 f01 = h2f(h01), f23 = h2f(h23);
            const uint32_t l01 = packh(v.y - f01.y, v.x - f01.x);
            const uint32_t l23 = packh(v.w - f23.y, v.z - f23.x);
            const int off = stage * STAGE + r * ROWB + c4 * 8;
            *(uint2*)(smem + off + 1 * TILEB) = make_uint2(h01, h23);
            *(uint2*)(smem + off + 2 * TILEB) = make_uint2(l01, l23);
        }
    };

    auto compute_stage = [&](int stage) {
        const uint32_t base = sb + stage * STAGE;
#pragma unroll
        for (int ks = 0; ks < 2; ks++) {
            const uint32_t koff = ks * 32;
            uint32_t ah[4][4];
#pragma unroll
            for (int mt = 0; mt < 4; mt++)
                ldm4(ah[mt], base + a_l + koff + mt * 16 * ROWB);
            uint32_t bh[2][4], bl[2][4];
#pragma unroll
            for (int j = 0; j < 2; j++)
                ldm4(bh[j], base + 1 * TILEB + b_l + koff + j * 16 * ROWB);
#pragma unroll
            for (int j = 0; j < 2; j++)
                ldm4(bl[j], base + 2 * TILEB + b_l + koff + j * 16 * ROWB);
            // hh sweep, then hl sweep: per-acc order hh -> hl preserved.
#pragma unroll
            for (int j = 0; j < 2; j++)
#pragma unroll
                for (int mt = 0; mt < 4; mt++) {
                    mma16816(acc[mt][2 * j],     ah[mt], bh[j][0], bh[j][1]);
                    mma16816(acc[mt][2 * j + 1], ah[mt], bh[j][2], bh[j][3]);
                }
#pragma unroll
            for (int j = 0; j < 2; j++)
#pragma unroll
                for (int mt = 0; mt < 4; mt++) {
                    mma16816(acc[mt][2 * j],     ah[mt], bl[j][0], bl[j][1]);
                    mma16816(acc[mt][2 * j + 1], ah[mt], bl[j][2], bl[j][3]);
                }
        }
    };

    load_stage(0, 0);

    for (int c = 0; c < nc; c++) {
        const int stage = c & 1;
        if (BF32) {
            asm volatile("cp.async.wait_group 0;" ::: "memory");
            __syncthreads();
            convert_stage(stage);
            __syncthreads();
            if (c + 1 < nc) load_stage(c + 1, stage ^ 1);
            compute_stage(stage);
        } else {
            if (c + 1 < nc) {
                load_stage(c + 1, stage ^ 1);
                asm volatile("cp.async.wait_group 1;" ::: "memory");
            } else {
                asm volatile("cp.async.wait_group 0;" ::: "memory");
            }
            __syncthreads();
            compute_stage(stage);
            __syncthreads();
        }
    }

    // ---- epilogue ----
    const int row0 = bm + wm * 64 + (lane >> 2);
    const int col0 = bn + wn * 32 + (lane & 3) * 2;
#pragma unroll
    for (int mt = 0; mt < 4; mt++) {
#pragma unroll
        for (int nt = 0; nt < 4; nt++) {
            const int r = row0 + mt * 16;
            const int cc = col0 + nt * 8;
            const float x0 = acc[mt][nt][0], x1 = acc[mt][nt][1];
            const float y0 = acc[mt][nt][2], y1 = acc[mt][nt][3];
            if (MODE == 0) {
                *(float2*)(Cf + (size_t)bz * sC + (size_t)r * N + cc) = make_float2(x0, x1);
                *(float2*)(Cf + (size_t)bz * sC + (size_t)(r + 8) * N + cc) = make_float2(y0, y1);
            } else {
                const uint32_t hx = packh(x1, x0);
                const float2 fx = h2f(hx);
                const uint32_t lx = packh(x1 - fx.y, x0 - fx.x);
                const uint32_t hy = packh(y1, y0);
                const float2 fy = h2f(hy);
                const uint32_t ly = packh(y1 - fy.y, y0 - fy.x);
                *(uint32_t*)(Chi + (size_t)bz * sC + (size_t)r * N + cc) = hx;
                *(uint32_t*)(Clo + (size_t)bz * sC + (size_t)r * N + cc) = lx;
                *(uint32_t*)(Chi + (size_t)bz * sC + (size_t)(r + 8) * N + cc) = hy;
                *(uint32_t*)(Clo + (size_t)bz * sC + (size_t)(r + 8) * N + cc) = ly;
            }
        }
    }
}

// ---------------- fp32 -> fp16 hi/lo split (flat; small weight arrays) ------
__global__ __launch_bounds__(256) void convert_split(
    const float4* __restrict__ in, uint2* __restrict__ hi, uint2* __restrict__ lo, size_t n4)
{
    size_t i = (size_t)blockIdx.x * blockDim.x + threadIdx.x;
    if (i >= n4) return;
    const float4 v = in[i];
    const uint32_t h01 = packh(v.y, v.x);
    const uint32_t h23 = packh(v.w, v.z);
    const float2 f01 = h2f(h01), f23 = h2f(h23);
    const uint32_t l01 = packh(v.y - f01.y, v.x - f01.x);
    const uint32_t l23 = packh(v.w - f23.y, v.z - f23.x);
    hi[i] = make_uint2(h01, h23);
    lo[i] = make_uint2(l01, l23);
}

// ---------------- fp32 [R,C] -> transposed f16 hi/lo [C,R], batched --------
__global__ __launch_bounds__(256) void transpose_split(
    const float* __restrict__ in, f16* __restrict__ ohi, f16* __restrict__ olo,
    int R, int C, size_t sI, size_t sO)
{
    __shared__ float t[32][33];
    in  += (size_t)blockIdx.z * sI;
    ohi += (size_t)blockIdx.z * sO;
    olo += (size_t)blockIdx.z * sO;
    const int r0 = blockIdx.y * 32, c0 = blockIdx.x * 32;
    const int tx = threadIdx.x, ty = threadIdx.y;
#pragma unroll
    for (int j = ty; j < 32; j += 8)
        t[j][tx] = in[(size_t)(r0 + j) * C + c0 + tx];
    __syncthreads();
    const int rr = (tx & 15) * 2;
    const int jb = ty + (tx >> 4) * 8;
#pragma unroll
    for (int it = 0; it < 2; it++) {
        const int j = jb + it * 16;
        const float v0 = t[rr][j], v1 = t[rr + 1][j];
        const uint32_t h = packh(v1, v0);
        const float2 f = h2f(h);
        const uint32_t l = packh(v1 - f.y, v0 - f.x);
        *(uint32_t*)(ohi + (size_t)(c0 + j) * R + r0 + rr) = h;
        *(uint32_t*)(olo + (size_t)(c0 + j) * R + r0 + rr) = l;
    }
}

// ---------------- w = Wk . bq ----------------
__global__ __launch_bounds__(256) void matvec_w(
    const float* __restrict__ Wk, const float* __restrict__ bq, float* __restrict__ w)
{
    const int d = blockIdx.x * 8 + (threadIdx.x >> 5);
    const int lane = threadIdx.x & 31;
    float s = 0.f;
    for (int e = lane; e < DQ; e += 32) s += Wk[(size_t)d * DQ + e] * bq[e];
#pragma unroll
    for (int o = 16; o > 0; o >>= 1) s += __shfl_xor_sync(0xFFFFFFFFu, s, o);
    if (lane == 0) w[d] = s;
}

// ---------------- vvec[r] = key[r,:] . w ----------------
__global__ __launch_bounds__(256) void matvec_v(
    const float* __restrict__ key, const float* __restrict__ w, float* __restrict__ vvec)
{
    const int r = blockIdx.x * 8 + (threadIdx.x >> 5);
    const int lane = threadIdx.x & 31;
    float s = 0.f;
    for (int d = lane; d < DK; d += 32) s += key[(size_t)r * DK + d] * w[d];
#pragma unroll
    for (int o = 16; o > 0; o >>= 1) s += __shfl_xor_sync(0xFFFFFFFFu, s, o);
    if (lane == 0) vvec[r] = s;
}

// ---------------- softmax rows (+column bias) -> f16 probs (hi only) --------
__global__ __launch_bounds__(256) void softmax_ph(
    const float* __restrict__ S, const float* __restrict__ vvec, f16* __restrict__ Phi)
{
    __shared__ float red[8];
    const size_t row = blockIdx.x;
    const float4* p4 = (const float4*)(S + row * (size_t)SLK);
    const float4* v4 = (const float4*)(vvec + (row >> 11) * (size_t)SLK);
    const int tid = threadIdx.x;

    float xv[8];
    {
        const float4 a = p4[tid], b = p4[tid + 256];
        const float4 va = v4[tid], vb = v4[tid + 256];
        xv[0] = a.x + va.x; xv[1] = a.y + va.y; xv[2] = a.z + va.z; xv[3] = a.w + va.w;
        xv[4] = b.x + vb.x; xv[5] = b.y + vb.y; xv[6] = b.z + vb.z; xv[7] = b.w + vb.w;
    }

    float m = -1e30f;
#pragma unroll
    for (int j = 0; j < 8; j++) m = fmaxf(m, xv[j]);
#pragma unroll
    for (int o = 16; o > 0; o >>= 1) m = fmaxf(m, __shfl_xor_sync(0xFFFFFFFFu, m, o));
    if ((tid & 31) == 0) red[tid >> 5] = m;
    __syncthreads();
    if (tid < 32) {
        float v = (tid < 8) ? red[tid] : -1e30f;
#pragma unroll
        for (int o = 4; o > 0; o >>= 1) v = fmaxf(v, __shfl_xor_sync(0xFFFFFFFFu, v, o));
        if (tid == 0) red[0] = v;
    }
    __syncthreads();
    m = red[0];
    __syncthreads();

    float s = 0.0f;
#pragma unroll
    for (int j = 0; j < 8; j++) { xv[j] = expf(xv[j] - m); s += xv[j]; }
#pragma unroll
    for (int o = 16; o > 0; o >>= 1) s += __shfl_xor_sync(0xFFFFFFFFu, s, o);
    if ((tid & 31) == 0) red[tid >> 5] = s;
    __syncthreads();
    if (tid < 32) {
        float v = (tid < 8) ? red[tid] : 0.0f;
#pragma unroll
        for (int o = 4; o > 0; o >>= 1) v += __shfl_xor_sync(0xFFFFFFFFu, v, o);
        if (tid == 0) red[0] = v;
    }
    __syncthreads();
    const float inv = 1.0f / red[0];

    uint2* out = (uint2*)(Phi + row * (size_t)SLK);
    out[tid]       = make_uint2(packh(xv[1] * inv, xv[0] * inv), packh(xv[3] * inv, xv[2] * inv));
    out[tid + 256] = make_uint2(packh(xv[5] * inv, xv[4] * inv), packh(xv[7] * inv, xv[6] * inv));
}

// ============================================================================
extern "C" void kernel_launch(void* const* d_in, const int* in_sizes, int n_in,
                              void* d_out, int out_size)
{
    const float* query = (const float*)d_in[0];
    const float* key   = (const float*)d_in[1];
    const float* value = (const float*)d_in[2];
    const float* Wq    = (const float*)d_in[3];
    const float* bq    = (const float*)d_in[4];
    const float* Wk    = (const float*)d_in[5];
    const float* bk    = (const float*)d_in[6];   // cancels in softmax (row-const)
    const float* Wv    = (const float*)d_in[7];
    const float* bv    = (const float*)d_in[8];
    float* out = (float*)d_out;
    (void)bk;

    f16 *wqh, *wql, *wkh, *wkl, *wvth, *wvtl;
    f16 *vth, *vtl, *mth, *mtl, *th, *uh, *ul, *ph;
    float *s, *wbq, *vvec;
    cudaGetSymbolAddress((void**)&wqh, g_wq_hi);  cudaGetSymbolAddress((void**)&wql, g_wq_lo);
    cudaGetSymbolAddress((void**)&wkh, g_wk_hi);  cudaGetSymbolAddress((void**)&wkl, g_wk_lo);
    cudaGetSymbolAddress((void**)&wvth, g_wvt_hi); cudaGetSymbolAddress((void**)&wvtl, g_wvt_lo);
    cudaGetSymbolAddress((void**)&vth, g_vt_hi);  cudaGetSymbolAddress((void**)&vtl, g_vt_lo);
    cudaGetSymbolAddress((void**)&mth, g_mt_hi);  cudaGetSymbolAddress((void**)&mtl, g_mt_lo);
    cudaGetSymbolAddress((void**)&th, g_t_hi);
    cudaGetSymbolAddress((void**)&uh, g_u_hi);    cudaGetSymbolAddress((void**)&ul, g_u_lo);
    cudaGetSymbolAddress((void**)&ph, g_p_hi);
    cudaGetSymbolAddress((void**)&s, g_s);
    cudaGetSymbolAddress((void**)&wbq, g_wbq);
    cudaGetSymbolAddress((void**)&vvec, g_vvec);

    const int SM_P3   = 2 * 4 * TILEB;            // 81920
    const int SM_P3F  = 2 * 4 * TILEB + 16384;    // 98304
    const int SM_P2   = 2 * 3 * TILEB;            // 61440
    const int SM_P2F  = 2 * 3 * TILEB + 16384;    // 77824
    cudaFuncSetAttribute((const void*)gemm_mma<1, 0>, cudaFuncAttributeMaxDynamicSharedMemorySize, SM_P3);
    cudaFuncSetAttribute((const void*)gemm_mma<2, 1>, cudaFuncAttributeMaxDynamicSharedMemorySize, SM_P3F);
    cudaFuncSetAttribute((const void*)gemm_mma<0, 0>, cudaFuncAttributeMaxDynamicSharedMemorySize, SM_P3);
    cudaFuncSetAttribute((const void*)gemm_mma2<0, 1>, cudaFuncAttributeMaxDynamicSharedMemorySize, SM_P2F);
    cudaFuncSetAttribute((const void*)gemm_mma2<1, 0>, cudaFuncAttributeMaxDynamicSharedMemorySize, SM_P2);

    const dim3 tb(32, 8, 1);

    // ---- weight splits (small) ----
    convert_split<<<(unsigned)((size_t)DQ * DQ / 4 / 256), 256>>>(
        (const float4*)Wq, (uint2*)wqh, (uint2*)wql, (size_t)DQ * DQ / 4);
    convert_split<<<(unsigned)((size_t)DK * DQ / 4 / 256), 256>>>(
        (const float4*)Wk, (uint2*)wkh, (uint2*)wkl, (size_t)DK * DQ / 4);
    transpose_split<<<dim3(DQ / 32, DV / 32, 1), tb>>>(Wv, wvth, wvtl, DV, DQ, 0, 0);
    transpose_split<<<dim3(DV / 32, SLK / 32, BB), tb>>>(
        value, vth, vtl, SLK, DV, (size_t)SLK * DV, (size_t)DV * SLK);

    // ---- bias correction vector (bq path; bk cancels) ----
    matvec_w<<<DK / 8, 256>>>(Wk, bq, wbq);
    matvec_v<<<MFLAT / 8, 256>>>(key, wbq, vvec);

    // ---- Mt = Wk Wq^T : [512,1024], P3, split out ----
    gemm_mma<1, 0><<<dim3(DQ / 128, DK / 128, 1), 256, SM_P3>>>(
        wkh, wkl, nullptr, wqh, wql, nullptr,
        nullptr, mth, mtl, DK, DQ, DQ, 0, 0, 0);

    // ---- T = q Mt^T : [16384,512], P3, A from fp32 query, f16-hi out ----
    gemm_mma<2, 1><<<dim3(DK / 128, MFLAT / 128, 1), 256, SM_P3F>>>(
        nullptr, nullptr, query, mth, mtl, nullptr,
        nullptr, th, nullptr, MFLAT, DK, DQ, 0, 0, 0);

    // ---- S = T key^T per batch : P2 (64x32 warps), B from fp32 key, fp32 out ----
    gemm_mma2<0, 1><<<dim3(SLK / 128, SLQ / 128, BB), 256, SM_P2F>>>(
        th, nullptr, nullptr, key,
        s, nullptr, nullptr,
        SLQ, SLK, DK, (size_t)SLQ * DK, (size_t)SLK * DK, (size_t)SLQ * SLK);

    // ---- softmax (+vvec column bias) -> f16 probs ----
    softmax_ph<<<BB * SLQ, 256>>>(s, vvec, ph);

    // ---- U = P value per batch : P2 (64x32 warps), split out ----
    gemm_mma2<1, 0><<<dim3(DV / 128, SLQ / 128, BB), 256, SM_P2>>>(
        ph, vth, vtl, nullptr,
        nullptr, uh, ul,
        SLQ, DV, SLK, (size_t)SLQ * SLK, (size_t)DV * SLK, (size_t)SLQ * DV);

    // ---- out = U Wv + bv per batch : P3, fp32 out ----
    gemm_mma<0, 0><<<dim3(DQ / 128, SLQ / 128, BB), 256, SM_P3>>>(
        uh, ul, nullptr, wvth, wvtl, bv,
        out, nullptr, nullptr,
        SLQ, DQ, DV, (size_t)SLQ * DV, 0, (size_t)SLQ * DQ);
}